// round 1
// baseline (speedup 1.0000x reference)
#include <cuda_runtime.h>
#include <math.h>

// Problem dims
#define B_DIM   16384
#define Z_DIM   128
#define H_DIM   512
#define HID_DIM 512
#define T_STEPS 32

// Scratch (device globals -- no allocation allowed)
__device__ __align__(256) float g_ctxproj[(size_t)B_DIM * HID_DIM]; // ctx @ W1[Z:,:] + b1
__device__ __align__(256) float g_h[(size_t)B_DIM * HID_DIM];      // hidden activations
__device__ __align__(256) float g_z[(size_t)B_DIM * Z_DIM];        // state z
__device__ __align__(256) float g_logw[(size_t)B_DIM * Z_DIM];     // accumulated log-weights
__device__ double g_sum;

// ---------------- SGEMM tile config ----------------
#define BM 128
#define BN 128
#define BK 16
#define TM 8
#define TN 8
#define NT 256   // (BM/TM)*(BN/TN)

// Computes acc = A[BMxK] @ B[KxBN]; A pre-offset to block row, Bmat pre-offset to block col.
__device__ __forceinline__ void gemm_128x128(
    const float* __restrict__ A, int lda,
    const float* __restrict__ Bmat, int ldb,
    int K, float (&acc)[TM][TN],
    float (*As)[BM], float (*Bs)[BN])
{
    const int tid = threadIdx.x;
    const int tx = tid & 15;
    const int ty = tid >> 4;

    const int a_row0 = tid >> 2;         // 0..63
    const int a_col4 = (tid & 3) * 4;    // 0,4,8,12
    const int b_row0 = tid >> 5;         // 0..7
    const int b_col4 = (tid & 31) * 4;   // 0..124

    for (int k0 = 0; k0 < K; k0 += BK) {
        // Load A tile (transposed into smem)
        #pragma unroll
        for (int half = 0; half < 2; half++) {
            int r = a_row0 + half * 64;
            float4 v = *reinterpret_cast<const float4*>(&A[(size_t)r * lda + k0 + a_col4]);
            As[a_col4 + 0][r] = v.x;
            As[a_col4 + 1][r] = v.y;
            As[a_col4 + 2][r] = v.z;
            As[a_col4 + 3][r] = v.w;
        }
        // Load B tile
        #pragma unroll
        for (int half = 0; half < 2; half++) {
            int r = b_row0 + half * 8;
            float4 v = *reinterpret_cast<const float4*>(&Bmat[(size_t)(k0 + r) * ldb + b_col4]);
            *reinterpret_cast<float4*>(&Bs[r][b_col4]) = v;
        }
        __syncthreads();

        #pragma unroll
        for (int k = 0; k < BK; k++) {
            float a[TM], b[TN];
            *reinterpret_cast<float4*>(&a[0]) = *reinterpret_cast<const float4*>(&As[k][ty * TM]);
            *reinterpret_cast<float4*>(&a[4]) = *reinterpret_cast<const float4*>(&As[k][ty * TM + 4]);
            *reinterpret_cast<float4*>(&b[0]) = *reinterpret_cast<const float4*>(&Bs[k][tx * TN]);
            *reinterpret_cast<float4*>(&b[4]) = *reinterpret_cast<const float4*>(&Bs[k][tx * TN + 4]);
            #pragma unroll
            for (int m = 0; m < TM; m++)
                #pragma unroll
                for (int n = 0; n < TN; n++)
                    acc[m][n] = fmaf(a[m], b[n], acc[m][n]);
        }
        __syncthreads();
    }
}

// ---------------- Kernel: init state ----------------
__global__ void init_kernel(const float* __restrict__ eps0, const float* __restrict__ sigma0)
{
    size_t i = (size_t)blockIdx.x * blockDim.x + threadIdx.x;
    if (i == 0) g_sum = 0.0;
    if (i < (size_t)B_DIM * Z_DIM) {
        g_z[i] = sigma0[0] * eps0[i];
        g_logw[i] = 0.0f;
    }
}

// ---------------- Kernel: ctx projection (once) ----------------
// g_ctxproj = ctx[B,512] @ W1[128:640, :] + b1
__global__ void __launch_bounds__(NT) ctxproj_kernel(
    const float* __restrict__ ctx, const float* __restrict__ W1, const float* __restrict__ b1)
{
    __shared__ float As[BK][BM];
    __shared__ float Bs[BK][BN];
    float acc[TM][TN] = {};

    const int blockCol = blockIdx.x;
    const int blockRow = blockIdx.y;
    const float* A = ctx + (size_t)blockRow * BM * H_DIM;
    const float* Bm = W1 + (size_t)Z_DIM * HID_DIM + blockCol * BN;

    gemm_128x128(A, H_DIM, Bm, HID_DIM, H_DIM, acc, As, Bs);

    const int tx = threadIdx.x & 15;
    const int ty = threadIdx.x >> 4;
    const int colbase = blockCol * BN + tx * TN;
    const int rowbase = blockRow * BM + ty * TM;

    float bv[TN];
    *reinterpret_cast<float4*>(&bv[0]) = *reinterpret_cast<const float4*>(&b1[colbase]);
    *reinterpret_cast<float4*>(&bv[4]) = *reinterpret_cast<const float4*>(&b1[colbase + 4]);

    #pragma unroll
    for (int m = 0; m < TM; m++) {
        size_t base = (size_t)(rowbase + m) * HID_DIM + colbase;
        float4 o0, o1;
        o0.x = acc[m][0] + bv[0]; o0.y = acc[m][1] + bv[1];
        o0.z = acc[m][2] + bv[2]; o0.w = acc[m][3] + bv[3];
        o1.x = acc[m][4] + bv[4]; o1.y = acc[m][5] + bv[5];
        o1.z = acc[m][6] + bv[6]; o1.w = acc[m][7] + bv[7];
        *reinterpret_cast<float4*>(&g_ctxproj[base])     = o0;
        *reinterpret_cast<float4*>(&g_ctxproj[base + 4]) = o1;
    }
}

// ---------------- Kernel: hidden = relu(z @ W1[:128,:] + ctxproj + te[t]) ----------------
__global__ void __launch_bounds__(NT) hidden_kernel(
    const float* __restrict__ W1, const float* __restrict__ temb, int t)
{
    __shared__ float As[BK][BM];
    __shared__ float Bs[BK][BN];
    float acc[TM][TN] = {};

    const int blockCol = blockIdx.x;
    const int blockRow = blockIdx.y;
    const float* A = g_z + (size_t)blockRow * BM * Z_DIM;
    const float* Bm = W1 + blockCol * BN;

    gemm_128x128(A, Z_DIM, Bm, HID_DIM, Z_DIM, acc, As, Bs);

    const int tx = threadIdx.x & 15;
    const int ty = threadIdx.x >> 4;
    const int colbase = blockCol * BN + tx * TN;
    const int rowbase = blockRow * BM + ty * TM;

    float te[TN];
    *reinterpret_cast<float4*>(&te[0]) = *reinterpret_cast<const float4*>(&temb[(size_t)t * HID_DIM + colbase]);
    *reinterpret_cast<float4*>(&te[4]) = *reinterpret_cast<const float4*>(&temb[(size_t)t * HID_DIM + colbase + 4]);

    #pragma unroll
    for (int m = 0; m < TM; m++) {
        size_t base = (size_t)(rowbase + m) * HID_DIM + colbase;
        float4 c0 = *reinterpret_cast<const float4*>(&g_ctxproj[base]);
        float4 c1 = *reinterpret_cast<const float4*>(&g_ctxproj[base + 4]);
        float v[TN];
        v[0] = acc[m][0] + c0.x + te[0];
        v[1] = acc[m][1] + c0.y + te[1];
        v[2] = acc[m][2] + c0.z + te[2];
        v[3] = acc[m][3] + c0.w + te[3];
        v[4] = acc[m][4] + c1.x + te[4];
        v[5] = acc[m][5] + c1.y + te[5];
        v[6] = acc[m][6] + c1.z + te[6];
        v[7] = acc[m][7] + c1.w + te[7];
        float4 o0, o1;
        o0.x = fmaxf(v[0], 0.f); o0.y = fmaxf(v[1], 0.f);
        o0.z = fmaxf(v[2], 0.f); o0.w = fmaxf(v[3], 0.f);
        o1.x = fmaxf(v[4], 0.f); o1.y = fmaxf(v[5], 0.f);
        o1.z = fmaxf(v[6], 0.f); o1.w = fmaxf(v[7], 0.f);
        *reinterpret_cast<float4*>(&g_h[base])     = o0;
        *reinterpret_cast<float4*>(&g_h[base + 4]) = o1;
    }
}

// ---------------- Kernel: u = h @ W2 + b2, then z/logw update ----------------
__global__ void __launch_bounds__(NT) update_kernel(
    const float* __restrict__ W2, const float* __restrict__ b2,
    const float* __restrict__ eps, const float* __restrict__ beta,
    const float* __restrict__ sigma0, int t)
{
    __shared__ float As[BK][BM];
    __shared__ float Bs[BK][BN];
    float acc[TM][TN] = {};

    const int blockCol = blockIdx.x; // always 0 (N = 128 = BN)
    const int blockRow = blockIdx.y;
    const float* A = g_h + (size_t)blockRow * BM * HID_DIM;
    const float* Bm = W2 + blockCol * BN;

    gemm_128x128(A, HID_DIM, Bm, Z_DIM, HID_DIM, acc, As, Bs);

    const int tx = threadIdx.x & 15;
    const int ty = threadIdx.x >> 4;
    const int colbase = blockCol * BN + tx * TN;
    const int rowbase = blockRow * BM + ty * TM;

    const float dt = 1.0f / T_STEPS;
    const float beta_f = beta[t];
    const float beta_b = beta[(t + T_STEPS - 1) % T_STEPS];
    const float s0 = sigma0[0];
    const float sig_f = sqrtf(2.0f * beta_f * dt) * s0;
    const float sig_b = sqrtf(2.0f * beta_b * dt) * s0;
    const float logdiff = logf(sig_f) - logf(sig_b);
    const float inv_sf = 1.0f / sig_f;
    const float inv_sb = 1.0f / sig_b;

    float bv[TN];
    *reinterpret_cast<float4*>(&bv[0]) = *reinterpret_cast<const float4*>(&b2[colbase]);
    *reinterpret_cast<float4*>(&bv[4]) = *reinterpret_cast<const float4*>(&b2[colbase + 4]);

    const float* eps_t = eps + (size_t)t * B_DIM * Z_DIM;

    #pragma unroll
    for (int m = 0; m < TM; m++) {
        size_t base = (size_t)(rowbase + m) * Z_DIM + colbase;
        float zp[TN], ev[TN], lw[TN];
        *reinterpret_cast<float4*>(&zp[0]) = *reinterpret_cast<const float4*>(&g_z[base]);
        *reinterpret_cast<float4*>(&zp[4]) = *reinterpret_cast<const float4*>(&g_z[base + 4]);
        *reinterpret_cast<float4*>(&ev[0]) = *reinterpret_cast<const float4*>(&eps_t[base]);
        *reinterpret_cast<float4*>(&ev[4]) = *reinterpret_cast<const float4*>(&eps_t[base + 4]);
        *reinterpret_cast<float4*>(&lw[0]) = *reinterpret_cast<const float4*>(&g_logw[base]);
        *reinterpret_cast<float4*>(&lw[4]) = *reinterpret_cast<const float4*>(&g_logw[base + 4]);

        float zn[TN];
        #pragma unroll
        for (int n = 0; n < TN; n++) {
            float u = acc[m][n] + bv[n];
            float mu_f = zp[n] + (beta_f * zp[n] + u) * dt;
            float z_next = mu_f + sig_f * ev[n];
            float mu_b = z_next - beta_b * z_next * dt;
            float a1 = (zp[n] - mu_b) * inv_sb;
            float a2 = (z_next - mu_f) * inv_sf;
            lw[n] += 0.5f * (a2 * a2 - a1 * a1) + logdiff;
            zn[n] = z_next;
        }
        *reinterpret_cast<float4*>(&g_z[base])        = *reinterpret_cast<float4*>(&zn[0]);
        *reinterpret_cast<float4*>(&g_z[base + 4])    = *reinterpret_cast<float4*>(&zn[4]);
        *reinterpret_cast<float4*>(&g_logw[base])     = *reinterpret_cast<float4*>(&lw[0]);
        *reinterpret_cast<float4*>(&g_logw[base + 4]) = *reinterpret_cast<float4*>(&lw[4]);
    }
}

// ---------------- Kernel: terminal correction + global reduction ----------------
__global__ void finalize_reduce(
    const float* __restrict__ eps0, const float* __restrict__ sigma0,
    const float* __restrict__ target_mu)
{
    const float s0 = sigma0[0];
    const float lg = logf(s0);
    double local = 0.0;
    const size_t N = (size_t)B_DIM * Z_DIM;
    for (size_t i = (size_t)blockIdx.x * blockDim.x + threadIdx.x; i < N;
         i += (size_t)gridDim.x * blockDim.x) {
        float zT = g_z[i];
        float d = zT - target_mu[i];
        float z0 = s0 * eps0[i];
        float a = z0 / s0;
        float v = g_logw[i] - 0.5f * d * d + 0.5f * a * a + lg;
        local += (double)v;
    }
    __shared__ double sd[256];
    sd[threadIdx.x] = local;
    __syncthreads();
    for (int s = 128; s > 0; s >>= 1) {
        if (threadIdx.x < s) sd[threadIdx.x] += sd[threadIdx.x + s];
        __syncthreads();
    }
    if (threadIdx.x == 0) atomicAdd(&g_sum, sd[0]);
}

__global__ void write_out(float* __restrict__ out)
{
    out[0] = (float)(g_sum / (double)B_DIM);
}

// ---------------- Host launcher ----------------
extern "C" void kernel_launch(void* const* d_in, const int* in_sizes, int n_in,
                              void* d_out, int out_size)
{
    (void)in_sizes; (void)n_in; (void)out_size;
    const float* ctx    = (const float*)d_in[0];
    const float* eps0   = (const float*)d_in[1];
    const float* eps    = (const float*)d_in[2];
    const float* beta   = (const float*)d_in[3];
    const float* sigma0 = (const float*)d_in[4];
    const float* W1     = (const float*)d_in[5];
    const float* b1     = (const float*)d_in[6];
    const float* W2     = (const float*)d_in[7];
    const float* b2     = (const float*)d_in[8];
    const float* temb   = (const float*)d_in[9];
    const float* tmu    = (const float*)d_in[10];
    float* out = (float*)d_out;

    init_kernel<<<(B_DIM * Z_DIM + 255) / 256, 256>>>(eps0, sigma0);
    ctxproj_kernel<<<dim3(HID_DIM / BN, B_DIM / BM), NT>>>(ctx, W1, b1);
    for (int t = 0; t < T_STEPS; t++) {
        hidden_kernel<<<dim3(HID_DIM / BN, B_DIM / BM), NT>>>(W1, temb, t);
        update_kernel<<<dim3(Z_DIM / BN, B_DIM / BM), NT>>>(W2, b2, eps, beta, sigma0, t);
    }
    finalize_reduce<<<1024, 256>>>(eps0, sigma0, tmu);
    write_out<<<1, 1>>>(out);
}

// round 2
// speedup vs baseline: 1.0031x; 1.0031x over previous
#include <cuda_runtime.h>
#include <math.h>

// Problem dims
#define B_DIM   16384
#define Z_DIM   128
#define H_DIM   512
#define HID_DIM 512
#define T_STEPS 32

// Scratch (device globals -- no allocation allowed)
__device__ __align__(256) float g_ctxproj[(size_t)B_DIM * HID_DIM]; // ctx @ W1[Z:,:] + b1
__device__ __align__(256) float g_h[(size_t)B_DIM * HID_DIM];      // hidden activations
__device__ __align__(256) float g_z[(size_t)B_DIM * Z_DIM];        // state z
__device__ __align__(256) float g_logw[(size_t)B_DIM * Z_DIM];     // accumulated log-weights
__device__ double g_sum;

// ---------------- SGEMM tile config ----------------
#define BM 128
#define BN 128
#define BK 16
#define TM 8
#define TN 8
#define NT 256   // (BM/TM)*(BN/TN)

// Computes acc = A[BMxK] @ B[KxBN]; A pre-offset to block row, Bmat pre-offset to block col.
__device__ __forceinline__ void gemm_128x128(
    const float* __restrict__ A, int lda,
    const float* __restrict__ Bmat, int ldb,
    int K, float (&acc)[TM][TN],
    float (*As)[BM], float (*Bs)[BN])
{
    const int tid = threadIdx.x;
    const int tx = tid & 15;
    const int ty = tid >> 4;

    const int a_row0 = tid >> 2;         // 0..63
    const int a_col4 = (tid & 3) * 4;    // 0,4,8,12
    const int b_row0 = tid >> 5;         // 0..7
    const int b_col4 = (tid & 31) * 4;   // 0..124

    for (int k0 = 0; k0 < K; k0 += BK) {
        // Load A tile (transposed into smem)
        #pragma unroll
        for (int half = 0; half < 2; half++) {
            int r = a_row0 + half * 64;
            float4 v = *reinterpret_cast<const float4*>(&A[(size_t)r * lda + k0 + a_col4]);
            As[a_col4 + 0][r] = v.x;
            As[a_col4 + 1][r] = v.y;
            As[a_col4 + 2][r] = v.z;
            As[a_col4 + 3][r] = v.w;
        }
        // Load B tile
        #pragma unroll
        for (int half = 0; half < 2; half++) {
            int r = b_row0 + half * 8;
            float4 v = *reinterpret_cast<const float4*>(&Bmat[(size_t)(k0 + r) * ldb + b_col4]);
            *reinterpret_cast<float4*>(&Bs[r][b_col4]) = v;
        }
        __syncthreads();

        #pragma unroll
        for (int k = 0; k < BK; k++) {
            float a[TM], b[TN];
            *reinterpret_cast<float4*>(&a[0]) = *reinterpret_cast<const float4*>(&As[k][ty * TM]);
            *reinterpret_cast<float4*>(&a[4]) = *reinterpret_cast<const float4*>(&As[k][ty * TM + 4]);
            *reinterpret_cast<float4*>(&b[0]) = *reinterpret_cast<const float4*>(&Bs[k][tx * TN]);
            *reinterpret_cast<float4*>(&b[4]) = *reinterpret_cast<const float4*>(&Bs[k][tx * TN + 4]);
            #pragma unroll
            for (int m = 0; m < TM; m++)
                #pragma unroll
                for (int n = 0; n < TN; n++)
                    acc[m][n] = fmaf(a[m], b[n], acc[m][n]);
        }
        __syncthreads();
    }
}

// ---------------- Kernel: init state ----------------
__global__ void init_kernel(const float* __restrict__ eps0, const float* __restrict__ sigma0)
{
    size_t i = (size_t)blockIdx.x * blockDim.x + threadIdx.x;
    if (i == 0) g_sum = 0.0;
    if (i < (size_t)B_DIM * Z_DIM) {
        g_z[i] = sigma0[0] * eps0[i];
        g_logw[i] = 0.0f;
    }
}

// ---------------- Kernel: ctx projection (once) ----------------
// g_ctxproj = ctx[B,512] @ W1[128:640, :] + b1
__global__ void __launch_bounds__(NT) ctxproj_kernel(
    const float* __restrict__ ctx, const float* __restrict__ W1, const float* __restrict__ b1)
{
    __shared__ float As[BK][BM];
    __shared__ float Bs[BK][BN];
    float acc[TM][TN] = {};

    const int blockCol = blockIdx.x;
    const int blockRow = blockIdx.y;
    const float* A = ctx + (size_t)blockRow * BM * H_DIM;
    const float* Bm = W1 + (size_t)Z_DIM * HID_DIM + blockCol * BN;

    gemm_128x128(A, H_DIM, Bm, HID_DIM, H_DIM, acc, As, Bs);

    const int tx = threadIdx.x & 15;
    const int ty = threadIdx.x >> 4;
    const int colbase = blockCol * BN + tx * TN;
    const int rowbase = blockRow * BM + ty * TM;

    float bv[TN];
    *reinterpret_cast<float4*>(&bv[0]) = *reinterpret_cast<const float4*>(&b1[colbase]);
    *reinterpret_cast<float4*>(&bv[4]) = *reinterpret_cast<const float4*>(&b1[colbase + 4]);

    #pragma unroll
    for (int m = 0; m < TM; m++) {
        size_t base = (size_t)(rowbase + m) * HID_DIM + colbase;
        float4 o0, o1;
        o0.x = acc[m][0] + bv[0]; o0.y = acc[m][1] + bv[1];
        o0.z = acc[m][2] + bv[2]; o0.w = acc[m][3] + bv[3];
        o1.x = acc[m][4] + bv[4]; o1.y = acc[m][5] + bv[5];
        o1.z = acc[m][6] + bv[6]; o1.w = acc[m][7] + bv[7];
        *reinterpret_cast<float4*>(&g_ctxproj[base])     = o0;
        *reinterpret_cast<float4*>(&g_ctxproj[base + 4]) = o1;
    }
}

// ---------------- Kernel: hidden = relu(z @ W1[:128,:] + ctxproj + te[t]) ----------------
__global__ void __launch_bounds__(NT) hidden_kernel(
    const float* __restrict__ W1, const float* __restrict__ temb, int t)
{
    __shared__ float As[BK][BM];
    __shared__ float Bs[BK][BN];
    float acc[TM][TN] = {};

    const int blockCol = blockIdx.x;
    const int blockRow = blockIdx.y;
    const float* A = g_z + (size_t)blockRow * BM * Z_DIM;
    const float* Bm = W1 + blockCol * BN;

    gemm_128x128(A, Z_DIM, Bm, HID_DIM, Z_DIM, acc, As, Bs);

    const int tx = threadIdx.x & 15;
    const int ty = threadIdx.x >> 4;
    const int colbase = blockCol * BN + tx * TN;
    const int rowbase = blockRow * BM + ty * TM;

    float te[TN];
    *reinterpret_cast<float4*>(&te[0]) = *reinterpret_cast<const float4*>(&temb[(size_t)t * HID_DIM + colbase]);
    *reinterpret_cast<float4*>(&te[4]) = *reinterpret_cast<const float4*>(&temb[(size_t)t * HID_DIM + colbase + 4]);

    #pragma unroll
    for (int m = 0; m < TM; m++) {
        size_t base = (size_t)(rowbase + m) * HID_DIM + colbase;
        float4 c0 = *reinterpret_cast<const float4*>(&g_ctxproj[base]);
        float4 c1 = *reinterpret_cast<const float4*>(&g_ctxproj[base + 4]);
        float v[TN];
        v[0] = acc[m][0] + c0.x + te[0];
        v[1] = acc[m][1] + c0.y + te[1];
        v[2] = acc[m][2] + c0.z + te[2];
        v[3] = acc[m][3] + c0.w + te[3];
        v[4] = acc[m][4] + c1.x + te[4];
        v[5] = acc[m][5] + c1.y + te[5];
        v[6] = acc[m][6] + c1.z + te[6];
        v[7] = acc[m][7] + c1.w + te[7];
        float4 o0, o1;
        o0.x = fmaxf(v[0], 0.f); o0.y = fmaxf(v[1], 0.f);
        o0.z = fmaxf(v[2], 0.f); o0.w = fmaxf(v[3], 0.f);
        o1.x = fmaxf(v[4], 0.f); o1.y = fmaxf(v[5], 0.f);
        o1.z = fmaxf(v[6], 0.f); o1.w = fmaxf(v[7], 0.f);
        *reinterpret_cast<float4*>(&g_h[base])     = o0;
        *reinterpret_cast<float4*>(&g_h[base + 4]) = o1;
    }
}

// ---------------- Kernel: u = h @ W2 + b2, then z/logw update ----------------
__global__ void __launch_bounds__(NT) update_kernel(
    const float* __restrict__ W2, const float* __restrict__ b2,
    const float* __restrict__ eps, const float* __restrict__ beta,
    const float* __restrict__ sigma0, int t)
{
    __shared__ float As[BK][BM];
    __shared__ float Bs[BK][BN];
    float acc[TM][TN] = {};

    const int blockCol = blockIdx.x; // always 0 (N = 128 = BN)
    const int blockRow = blockIdx.y;
    const float* A = g_h + (size_t)blockRow * BM * HID_DIM;
    const float* Bm = W2 + blockCol * BN;

    gemm_128x128(A, HID_DIM, Bm, Z_DIM, HID_DIM, acc, As, Bs);

    const int tx = threadIdx.x & 15;
    const int ty = threadIdx.x >> 4;
    const int colbase = blockCol * BN + tx * TN;
    const int rowbase = blockRow * BM + ty * TM;

    const float dt = 1.0f / T_STEPS;
    const float beta_f = beta[t];
    const float beta_b = beta[(t + T_STEPS - 1) % T_STEPS];
    const float s0 = sigma0[0];
    const float sig_f = sqrtf(2.0f * beta_f * dt) * s0;
    const float sig_b = sqrtf(2.0f * beta_b * dt) * s0;
    const float logdiff = logf(sig_f) - logf(sig_b);
    const float inv_sf = 1.0f / sig_f;
    const float inv_sb = 1.0f / sig_b;

    float bv[TN];
    *reinterpret_cast<float4*>(&bv[0]) = *reinterpret_cast<const float4*>(&b2[colbase]);
    *reinterpret_cast<float4*>(&bv[4]) = *reinterpret_cast<const float4*>(&b2[colbase + 4]);

    const float* eps_t = eps + (size_t)t * B_DIM * Z_DIM;

    #pragma unroll
    for (int m = 0; m < TM; m++) {
        size_t base = (size_t)(rowbase + m) * Z_DIM + colbase;
        float zp[TN], ev[TN], lw[TN];
        *reinterpret_cast<float4*>(&zp[0]) = *reinterpret_cast<const float4*>(&g_z[base]);
        *reinterpret_cast<float4*>(&zp[4]) = *reinterpret_cast<const float4*>(&g_z[base + 4]);
        *reinterpret_cast<float4*>(&ev[0]) = *reinterpret_cast<const float4*>(&eps_t[base]);
        *reinterpret_cast<float4*>(&ev[4]) = *reinterpret_cast<const float4*>(&eps_t[base + 4]);
        *reinterpret_cast<float4*>(&lw[0]) = *reinterpret_cast<const float4*>(&g_logw[base]);
        *reinterpret_cast<float4*>(&lw[4]) = *reinterpret_cast<const float4*>(&g_logw[base + 4]);

        float zn[TN];
        #pragma unroll
        for (int n = 0; n < TN; n++) {
            float u = acc[m][n] + bv[n];
            float mu_f = zp[n] + (beta_f * zp[n] + u) * dt;
            float z_next = mu_f + sig_f * ev[n];
            float mu_b = z_next - beta_b * z_next * dt;
            float a1 = (zp[n] - mu_b) * inv_sb;
            float a2 = (z_next - mu_f) * inv_sf;
            lw[n] += 0.5f * (a2 * a2 - a1 * a1) + logdiff;
            zn[n] = z_next;
        }
        *reinterpret_cast<float4*>(&g_z[base])        = *reinterpret_cast<float4*>(&zn[0]);
        *reinterpret_cast<float4*>(&g_z[base + 4])    = *reinterpret_cast<float4*>(&zn[4]);
        *reinterpret_cast<float4*>(&g_logw[base])     = *reinterpret_cast<float4*>(&lw[0]);
        *reinterpret_cast<float4*>(&g_logw[base + 4]) = *reinterpret_cast<float4*>(&lw[4]);
    }
}

// ---------------- Kernel: terminal correction + global reduction ----------------
__global__ void finalize_reduce(
    const float* __restrict__ eps0, const float* __restrict__ sigma0,
    const float* __restrict__ target_mu)
{
    const float s0 = sigma0[0];
    const float lg = logf(s0);
    double local = 0.0;
    const size_t N = (size_t)B_DIM * Z_DIM;
    for (size_t i = (size_t)blockIdx.x * blockDim.x + threadIdx.x; i < N;
         i += (size_t)gridDim.x * blockDim.x) {
        float zT = g_z[i];
        float d = zT - target_mu[i];
        float z0 = s0 * eps0[i];
        float a = z0 / s0;
        float v = g_logw[i] - 0.5f * d * d + 0.5f * a * a + lg;
        local += (double)v;
    }
    __shared__ double sd[256];
    sd[threadIdx.x] = local;
    __syncthreads();
    for (int s = 128; s > 0; s >>= 1) {
        if (threadIdx.x < s) sd[threadIdx.x] += sd[threadIdx.x + s];
        __syncthreads();
    }
    if (threadIdx.x == 0) atomicAdd(&g_sum, sd[0]);
}

__global__ void write_out(float* __restrict__ out)
{
    out[0] = (float)(g_sum / (double)B_DIM);
}

// ---------------- Host launcher ----------------
extern "C" void kernel_launch(void* const* d_in, const int* in_sizes, int n_in,
                              void* d_out, int out_size)
{
    (void)in_sizes; (void)n_in; (void)out_size;
    const float* ctx    = (const float*)d_in[0];
    const float* eps0   = (const float*)d_in[1];
    const float* eps    = (const float*)d_in[2];
    const float* beta   = (const float*)d_in[3];
    const float* sigma0 = (const float*)d_in[4];
    const float* W1     = (const float*)d_in[5];
    const float* b1     = (const float*)d_in[6];
    const float* W2     = (const float*)d_in[7];
    const float* b2     = (const float*)d_in[8];
    const float* temb   = (const float*)d_in[9];
    const float* tmu    = (const float*)d_in[10];
    float* out = (float*)d_out;

    init_kernel<<<(B_DIM * Z_DIM + 255) / 256, 256>>>(eps0, sigma0);
    ctxproj_kernel<<<dim3(HID_DIM / BN, B_DIM / BM), NT>>>(ctx, W1, b1);
    for (int t = 0; t < T_STEPS; t++) {
        hidden_kernel<<<dim3(HID_DIM / BN, B_DIM / BM), NT>>>(W1, temb, t);
        update_kernel<<<dim3(Z_DIM / BN, B_DIM / BM), NT>>>(W2, b2, eps, beta, sigma0, t);
    }
    finalize_reduce<<<1024, 256>>>(eps0, sigma0, tmu);
    write_out<<<1, 1>>>(out);
}